// round 5
// baseline (speedup 1.0000x reference)
#include <cuda_runtime.h>
#include <cuda_bf16.h>

typedef unsigned long long u64;
typedef unsigned int u32;

#define MAXN 250048

// Scratch (allocation-free rule: __device__ globals)
__device__ float g_X  [(size_t)MAXN * 64];
__device__ float g_F1 [(size_t)MAXN * 64];
__device__ float g_D0 [(size_t)MAXN * 32];
__device__ float g_D1 [(size_t)MAXN * 32];
__device__ float g_A8 [(size_t)MAXN * 8];
__device__ float g_T8 [(size_t)MAXN * 8];
__device__ float g_T8B[(size_t)MAXN * 8];
__device__ int   g_iT1[(size_t)MAXN * 27];
__device__ int   g_iT2[(size_t)MAXN * 27];
__device__ int   g_iTd[(size_t)MAXN * 8];
// fragment-packed tf32 weights
__device__ float g_WF1[27 * 4096];   // conv1
__device__ float g_WFd[8 * 2048];    // down
__device__ float g_WF0[81 * 256];    // rw00 (3 blocks as K=81)
__device__ float g_WF4[27 * 256];    // enc4
__device__ float g_WFp[3 * 256];     // rw10 pointwise (3 blocks, K=1)

__device__ __forceinline__ u64 pack2(float x) {
    u64 r;
    asm("mov.b64 %0, {%1, %1};" : "=l"(r) : "r"(__float_as_uint(x)));
    return r;
}
__device__ __forceinline__ void fma2(u64& acc, u64 a, u64 b) {
    asm("fma.rn.f32x2 %0, %1, %2, %0;" : "+l"(acc) : "l"(a), "l"(b));
}
__device__ __forceinline__ float2 unpack2(u64 v) {
    float2 r;
    r.x = __uint_as_float((u32)(v & 0xffffffffull));
    r.y = __uint_as_float((u32)(v >> 32));
    return r;
}
__device__ __forceinline__ u32 smem_u32(const void* p) {
    return (u32)__cvta_generic_to_shared(p);
}
__device__ __forceinline__ void cpasync16(u32 dst, const void* src, u32 ssz) {
    asm volatile("cp.async.ca.shared.global [%0], [%1], 16, %2;\n"
                 :: "r"(dst), "l"(src), "r"(ssz));
}
__device__ __forceinline__ void cp_commit() {
    asm volatile("cp.async.commit_group;\n");
}
template<int N>
__device__ __forceinline__ void cp_wait() {
    asm volatile("cp.async.wait_group %0;\n" :: "n"(N));
}
__device__ __forceinline__ float rna_tf32(float x) {
    u32 y;
    asm("cvt.rna.tf32.f32 %0, %1;" : "=r"(y) : "f"(x));
    return __uint_as_float(y);
}
__device__ __forceinline__ void mma8(float4& d, const float* a, float2 b) {
    asm("mma.sync.aligned.m16n8k8.row.col.f32.tf32.tf32.f32 "
        "{%0,%1,%2,%3}, {%4,%5,%6,%7}, {%8,%9}, {%0,%1,%2,%3};"
        : "+f"(d.x), "+f"(d.y), "+f"(d.z), "+f"(d.w)
        : "r"(__float_as_uint(a[0])), "r"(__float_as_uint(a[1])),
          "r"(__float_as_uint(a[2])), "r"(__float_as_uint(a[3])),
          "r"(__float_as_uint(b.x)),  "r"(__float_as_uint(b.y)));
}

// ---------------------------------------------------------------------------
__global__ void transpose_idx(const int* __restrict__ in, int* __restrict__ outT,
                              int Npt, int K)
{
    int p = blockIdx.x * blockDim.x + threadIdx.x;
    if (p < Npt)
        for (int k = 0; k < K; k++)
            outT[(size_t)k * Npt + p] = in[(size_t)p * K + k];
}

// W[k][ci][co] fp32 -> tf32 B-fragment order
__global__ void prep_wfrag(const float* __restrict__ W, float* __restrict__ Wf,
                           int K, int CIN, int COUT)
{
    int Q = CIN / 8, NT = COUT / 8;
    int total = K * Q * NT * 64;
    int e = blockIdx.x * 256 + threadIdx.x;
    if (e >= total) return;
    int j = e & 1;
    int lane = (e >> 1) & 31;
    int r = e >> 6;
    int nt = r % NT; r /= NT;
    int q = r % Q;  int k = r / Q;
    int ci = q * 8 + (lane & 3) + 4 * j;
    int co = nt * 8 + (lane >> 2);
    Wf[e] = rna_tf32(W[((size_t)k * CIN + ci) * COUT + co]);
}

// ---------------------------------------------------------------------------
// tf32 mma.sync gather-GEMM sparse conv.  NTHR points/CTA (=NTHR threads),
// NTHR/32 warps; warp w -> rows [32w,32w+32) as 2 m16 tiles.
// cp.async double-buffered over K offsets; accumulate across offsets in regs.
// FUSEPW: at k==CK (center offset), also accumulate pointwise Wp (COUT=8)
// producing tp = relu(in[p] @ Wp + Bp) -> Tout.
// ---------------------------------------------------------------------------
template<int K, int CIN, int COUT, int NTHR, bool RELU, bool CVTOUT,
         bool FUSEPW, int CK>
__global__ void __launch_bounds__(NTHR)
tf32_conv(const float* __restrict__ X, const int* __restrict__ idxT,
          const float* __restrict__ Wf, const float* __restrict__ Bb,
          float* __restrict__ out,
          const float* __restrict__ Wp, const float* __restrict__ Bp,
          float* __restrict__ Tout, int Nout)
{
    constexpr int Q    = CIN / 8;
    constexpr int NT   = COUT / 8;
    constexpr int ASTG = NTHR * CIN;
    constexpr int WSTG = Q * NT * 64;
    constexpr int C4U  = CIN / 4;

    extern __shared__ float sm[];
    float* A0 = sm;
    float* A1 = sm + ASTG;
    float* W0 = sm + 2 * ASTG;
    float* W1 = W0 + WSTG;

    const int tid = threadIdx.x, wid = tid >> 5, lane = tid & 31;
    const int r7 = lane >> 2;
    const int cl = lane & 3;
    const int p0 = blockIdx.x * NTHR;
    const int gp = p0 + tid;
    const bool pv = gp < Nout;

    const u32 ab0 = smem_u32(A0), ab1 = smem_u32(A1);
    const u32 wb0 = smem_u32(W0), wb1 = smem_u32(W1);

    // pointwise B fragments (small, L2-resident)
    float2 b10[FUSEPW ? Q : 1];
    if (FUSEPW) {
#pragma unroll
        for (int q = 0; q < Q; q++)
            b10[q] = *(const float2*)(Wp + (q * 32 + lane) * 2);
    }

    auto prefetch = [&](int k, int b) {
        int src = pv ? idxT[(size_t)k * Nout + gp] : -1;
        const float* srow = X + (size_t)(src >= 0 ? src : 0) * CIN;
        u32 ssz = (src >= 0) ? 16u : 0u;
        u32 base = (b ? ab1 : ab0) + (u32)tid * (CIN * 4);
#pragma unroll
        for (int c4 = 0; c4 < C4U; c4++)
            cpasync16(base + ((u32)(c4 ^ (tid & 7)) << 4), srow + 4 * c4, ssz);
        const float4* wg = (const float4*)(Wf + (size_t)k * WSTG);
        u32 wdst = b ? wb1 : wb0;
        for (int e = tid; e < WSTG / 4; e += NTHR)
            cpasync16(wdst + 16u * e, wg + e, 16);
    };

    prefetch(0, 0);
    cp_commit();

    float4 acc[2][NT];
#pragma unroll
    for (int m = 0; m < 2; m++)
#pragma unroll
        for (int nt = 0; nt < NT; nt++)
            acc[m][nt] = make_float4(0.f, 0.f, 0.f, 0.f);
    float4 acc2[2];
    acc2[0] = acc2[1] = make_float4(0.f, 0.f, 0.f, 0.f);

#pragma unroll 1
    for (int k = 0; k < K; k++) {
        __syncthreads();
        if (k + 1 < K) { prefetch(k + 1, (k + 1) & 1); cp_commit(); cp_wait<1>(); }
        else           { cp_wait<0>(); }
        __syncthreads();

        const float* A  = (k & 1) ? A1 : A0;
        const float* Wk = (k & 1) ? W1 : W0;

#pragma unroll
        for (int q = 0; q < Q; q++) {
            const int c4a = ((2 * q) ^ r7) << 2;
            const int c4b = ((2 * q + 1) ^ r7) << 2;
            float a[2][4];
#pragma unroll
            for (int m = 0; m < 2; m++) {
                const int rl = wid * 32 + m * 16 + r7;
                a[m][0] = A[rl * CIN + c4a + cl];
                a[m][1] = A[(rl + 8) * CIN + c4a + cl];
                a[m][2] = A[rl * CIN + c4b + cl];
                a[m][3] = A[(rl + 8) * CIN + c4b + cl];
            }
#pragma unroll
            for (int nt = 0; nt < NT; nt++) {
                float2 b = *(const float2*)(Wk + ((q * NT + nt) * 32 + lane) * 2);
                mma8(acc[0][nt], a[0], b);
                mma8(acc[1][nt], a[1], b);
            }
            if (FUSEPW && k == CK) {
                mma8(acc2[0], a[0], b10[q]);
                mma8(acc2[1], a[1], b10[q]);
            }
        }
    }

    // epilogue
#pragma unroll
    for (int m = 0; m < 2; m++) {
        const int rlo = p0 + wid * 32 + m * 16 + r7;
        const int rhi = rlo + 8;
#pragma unroll
        for (int nt = 0; nt < NT; nt++) {
            const int c0 = nt * 8 + 2 * cl;
            const float b0 = Bb[c0], b1 = Bb[c0 + 1];
            float2 v0 = make_float2(acc[m][nt].x + b0, acc[m][nt].y + b1);
            float2 v1 = make_float2(acc[m][nt].z + b0, acc[m][nt].w + b1);
            if (RELU) {
                v0.x = fmaxf(v0.x, 0.f); v0.y = fmaxf(v0.y, 0.f);
                v1.x = fmaxf(v1.x, 0.f); v1.y = fmaxf(v1.y, 0.f);
            }
            if (CVTOUT) {
                v0.x = rna_tf32(v0.x); v0.y = rna_tf32(v0.y);
                v1.x = rna_tf32(v1.x); v1.y = rna_tf32(v1.y);
            }
            if (rlo < Nout) *(float2*)(out + (size_t)rlo * COUT + c0) = v0;
            if (rhi < Nout) *(float2*)(out + (size_t)rhi * COUT + c0) = v1;
        }
        if (FUSEPW) {
            const int c0 = 2 * cl;
            const float b0 = Bp[c0], b1 = Bp[c0 + 1];
            float2 v0 = make_float2(fmaxf(acc2[m].x + b0, 0.f),
                                    fmaxf(acc2[m].y + b1, 0.f));
            float2 v1 = make_float2(fmaxf(acc2[m].z + b0, 0.f),
                                    fmaxf(acc2[m].w + b1, 0.f));
            if (rlo < Nout) *(float2*)(Tout + (size_t)rlo * 8 + c0) = v0;
            if (rhi < Nout) *(float2*)(Tout + (size_t)rhi * 8 + c0) = v1;
        }
    }
}

// ---------------------------------------------------------------------------
// Dual CIN=8 sparse conv over the same index map:
//   out0 = conv(A8, W01) + b01 + Rin[:, :16]  -> ob[:, :16]      (COUT=16)
//   T8B  = relu(conv(T8, W11) + b11)                              (COUT=8)
// One idx walk, register double-buffered rows from both feature arrays.
// ---------------------------------------------------------------------------
template<int K>
__global__ void __launch_bounds__(256)
spconv_dual8(const float* __restrict__ A8, const float* __restrict__ T8,
             const int* __restrict__ idxT,
             const float* __restrict__ W01, const float* __restrict__ b01,
             const float* __restrict__ W11, const float* __restrict__ b11,
             const float* __restrict__ Rin, float* __restrict__ ob,
             float* __restrict__ T8B, int Nout)
{
    __shared__ float Wsh0[K * 8 * 16];
    __shared__ float Wsh1[K * 8 * 8];
    for (int e = threadIdx.x; e < K * 8 * 16; e += 256) Wsh0[e] = W01[e];
    for (int e = threadIdx.x; e < K * 8 * 8; e += 256)  Wsh1[e] = W11[e];
    __syncthreads();

    const int p = blockIdx.x * 256 + threadIdx.x;
    if (p >= Nout) return;

    u64 acc0[8], acc1[4];
#pragma unroll
    for (int c = 0; c < 8; c++) acc0[c] = 0ull;
#pragma unroll
    for (int c = 0; c < 4; c++) acc1[c] = 0ull;

    const float4 z4 = make_float4(0.f, 0.f, 0.f, 0.f);
    int s_nxt = (K > 1) ? idxT[(size_t)Nout + p] : -1;
    int s0 = idxT[p];
    float4 a0 = z4, a1 = z4, t0 = z4, t1 = z4;
    if (s0 >= 0) {
        const float4* ra = (const float4*)(A8 + (size_t)s0 * 8);
        a0 = ra[0]; a1 = ra[1];
        const float4* rt = (const float4*)(T8 + (size_t)s0 * 8);
        t0 = rt[0]; t1 = rt[1];
    }

#pragma unroll 1
    for (int k = 0; k < K; k++) {
        float4 na0 = z4, na1 = z4, nt0 = z4, nt1 = z4;
        if (k + 1 < K) {
            if (s_nxt >= 0) {
                const float4* ra = (const float4*)(A8 + (size_t)s_nxt * 8);
                na0 = ra[0]; na1 = ra[1];
                const float4* rt = (const float4*)(T8 + (size_t)s_nxt * 8);
                nt0 = rt[0]; nt1 = rt[1];
            }
            s_nxt = (k + 2 < K) ? idxT[(size_t)(k + 2) * Nout + p] : -1;
        }
        {
            const float* wk = Wsh0 + k * 8 * 16;
            const float ga[8] = { a0.x, a0.y, a0.z, a0.w, a1.x, a1.y, a1.z, a1.w };
#pragma unroll
            for (int ci = 0; ci < 8; ci++) {
                u64 g2 = pack2(ga[ci]);
                const u64* wr = (const u64*)(wk + ci * 16);
#pragma unroll
                for (int cc = 0; cc < 8; cc++) fma2(acc0[cc], g2, wr[cc]);
            }
        }
        {
            const float* wk = Wsh1 + k * 8 * 8;
            const float gt[8] = { t0.x, t0.y, t0.z, t0.w, t1.x, t1.y, t1.z, t1.w };
#pragma unroll
            for (int ci = 0; ci < 8; ci++) {
                u64 g2 = pack2(gt[ci]);
                const u64* wr = (const u64*)(wk + ci * 8);
#pragma unroll
                for (int cc = 0; cc < 4; cc++) fma2(acc1[cc], g2, wr[cc]);
            }
        }
        a0 = na0; a1 = na1; t0 = nt0; t1 = nt1;
    }

    // out0 + resid -> ob[:, :16]
    float* op = ob + (size_t)p * 32;
#pragma unroll
    for (int q = 0; q < 4; q++) {
        float2 v0 = unpack2(acc0[2 * q]);
        float2 v1 = unpack2(acc0[2 * q + 1]);
        float4 o = make_float4(v0.x + b01[4 * q], v0.y + b01[4 * q + 1],
                               v1.x + b01[4 * q + 2], v1.y + b01[4 * q + 3]);
        float4 r = *(const float4*)(Rin + (size_t)p * 32 + 4 * q);
        o.x += r.x; o.y += r.y; o.z += r.z; o.w += r.w;
        *(float4*)(op + 4 * q) = o;
    }
    // relu(conv T8) -> T8B
    float* tp = T8B + (size_t)p * 8;
#pragma unroll
    for (int q = 0; q < 2; q++) {
        float2 v0 = unpack2(acc1[2 * q]);
        float2 v1 = unpack2(acc1[2 * q + 1]);
        float4 o = make_float4(fmaxf(v0.x + b11[4 * q], 0.f),
                               fmaxf(v0.y + b11[4 * q + 1], 0.f),
                               fmaxf(v1.x + b11[4 * q + 2], 0.f),
                               fmaxf(v1.y + b11[4 * q + 3], 0.f));
        *(float4*)(tp + 4 * q) = o;
    }
}

// ---------------------------------------------------------------------------
// Pointwise conv
// ---------------------------------------------------------------------------
template<int CIN, int COUT, bool RELU, bool RESID, int OSTRIDE, int OCOFF>
__global__ void pw_kernel(const float* __restrict__ X, const float* __restrict__ W,
                          const float* __restrict__ B, const float* __restrict__ R,
                          float* __restrict__ out, int Nout)
{
    __shared__ float Wsh[CIN * COUT];
    for (int e = threadIdx.x; e < CIN * COUT; e += blockDim.x) Wsh[e] = W[e];
    __syncthreads();

    int p = blockIdx.x * blockDim.x + threadIdx.x;
    if (p >= Nout) return;

    float acc[COUT];
#pragma unroll
    for (int c = 0; c < COUT; c++) acc[c] = B[c];

    const float4* xr = (const float4*)(X + (size_t)p * CIN);
#pragma unroll
    for (int c4 = 0; c4 < CIN / 4; c4++) {
        float4 v = xr[c4];
        const float* w0 = Wsh + (4 * c4) * COUT;
#pragma unroll
        for (int c = 0; c < COUT; c++) {
            acc[c] += v.x * w0[c] + v.y * w0[COUT + c]
                    + v.z * w0[2 * COUT + c] + v.w * w0[3 * COUT + c];
        }
    }
#pragma unroll
    for (int c = 0; c < COUT; c++) {
        float v = acc[c];
        if (RESID) v += R[(size_t)p * OSTRIDE + OCOFF + c];
        if (RELU)  v = fmaxf(v, 0.f);
        out[(size_t)p * OSTRIDE + OCOFF + c] = v;
    }
}

template<bool CVT>
__global__ void add_kernel(const float* __restrict__ a, const float* __restrict__ b,
                           float* __restrict__ o, long long n4)
{
    long long i = blockIdx.x * (long long)blockDim.x + threadIdx.x;
    if (i < n4) {
        float4 x = ((const float4*)a)[i];
        float4 y = ((const float4*)b)[i];
        x.x += y.x; x.y += y.y; x.z += y.z; x.w += y.w;
        if (CVT) {
            x.x = rna_tf32(x.x); x.y = rna_tf32(x.y);
            x.z = rna_tf32(x.z); x.w = rna_tf32(x.w);
        }
        ((float4*)o)[i] = x;
    }
}

// ---------------------------------------------------------------------------
template<int K, int CIN, int COUT, int NTHR, bool RELU, bool CVTOUT,
         bool FUSEPW, int CK>
static void launch_tf32(const float* X, const int* idxT, const float* Wf,
                        const float* B, float* out,
                        const float* Wp, const float* Bp, float* Tout, int Nout)
{
    constexpr int SMEM = (2 * NTHR * CIN + 2 * (CIN / 8) * (COUT / 8) * 64) * 4;
    auto kfn = tf32_conv<K, CIN, COUT, NTHR, RELU, CVTOUT, FUSEPW, CK>;
    cudaFuncSetAttribute(kfn, cudaFuncAttributeMaxDynamicSharedMemorySize, SMEM);
    int grid = (Nout + NTHR - 1) / NTHR;
    kfn<<<grid, NTHR, SMEM>>>(X, idxT, Wf, B, out, Wp, Bp, Tout, Nout);
}

extern "C" void kernel_launch(void* const* d_in, const int* in_sizes, int n_in,
                              void* d_out, int out_size)
{
    const float* x_feat = (const float*)d_in[0];
    const float* f1_ref = (const float*)d_in[1];
    const float* w1   = (const float*)d_in[2];
    const float* b1   = (const float*)d_in[3];
    const float* wd   = (const float*)d_in[4];
    const float* bd   = (const float*)d_in[5];
    const float* rw00 = (const float*)d_in[6];
    const float* rb00 = (const float*)d_in[7];
    const float* rw01 = (const float*)d_in[8];
    const float* rb01 = (const float*)d_in[9];
    const float* rw10 = (const float*)d_in[10];
    const float* rb10 = (const float*)d_in[11];
    const float* rw11 = (const float*)d_in[12];
    const float* rb11 = (const float*)d_in[13];
    const float* rw12 = (const float*)d_in[14];
    const float* rb12 = (const float*)d_in[15];
    const float* w4   = (const float*)d_in[16];
    const float* b4   = (const float*)d_in[17];
    const int* idx1 = (const int*)d_in[18];
    const int* idxd = (const int*)d_in[19];
    const int* idx2 = (const int*)d_in[20];

    int N  = in_sizes[0] / 64;
    int N2 = in_sizes[19] / 8;

    float *X, *F1, *D0, *D1, *A8, *T8, *T8B;
    float *WF1, *WFd, *WF0, *WF4, *WFp;
    int *iT1, *iT2, *iTd;
    cudaGetSymbolAddress((void**)&X,   g_X);
    cudaGetSymbolAddress((void**)&F1,  g_F1);
    cudaGetSymbolAddress((void**)&D0,  g_D0);
    cudaGetSymbolAddress((void**)&D1,  g_D1);
    cudaGetSymbolAddress((void**)&A8,  g_A8);
    cudaGetSymbolAddress((void**)&T8,  g_T8);
    cudaGetSymbolAddress((void**)&T8B, g_T8B);
    cudaGetSymbolAddress((void**)&iT1, g_iT1);
    cudaGetSymbolAddress((void**)&iT2, g_iT2);
    cudaGetSymbolAddress((void**)&iTd, g_iTd);
    cudaGetSymbolAddress((void**)&WF1, g_WF1);
    cudaGetSymbolAddress((void**)&WFd, g_WFd);
    cudaGetSymbolAddress((void**)&WF0, g_WF0);
    cudaGetSymbolAddress((void**)&WF4, g_WF4);
    cudaGetSymbolAddress((void**)&WFp, g_WFp);

    // prep
    transpose_idx<<<(N  + 255) / 256, 256>>>(idx1, iT1, N,  27);
    transpose_idx<<<(N2 + 255) / 256, 256>>>(idxd, iTd, N2, 8);
    transpose_idx<<<(N2 + 255) / 256, 256>>>(idx2, iT2, N2, 27);
    prep_wfrag<<<(27 * 4096 + 255) / 256, 256>>>(w1,   WF1, 27, 64, 64);
    prep_wfrag<<<(8 * 2048 + 255) / 256, 256>>>(wd,    WFd, 8,  64, 32);
    prep_wfrag<<<(81 * 256 + 255) / 256, 256>>>(rw00,  WF0, 81, 32, 8);
    prep_wfrag<<<(27 * 256 + 255) / 256, 256>>>(w4,    WF4, 27, 32, 8);
    prep_wfrag<<<(3 * 256 + 255) / 256, 256>>>(rw10,   WFp, 3,  32, 8);

    // x = tf32(x_feat + f1_ref)
    long long n4 = (long long)N * 16;
    add_kernel<true><<<(int)((n4 + 255) / 256), 256>>>(x_feat, f1_ref, X, n4);

    // conv1: K=27, 64->64, relu (rounds output to tf32 for `down`)
    launch_tf32<27, 64, 64, 256, true, true, false, 0>(
        X, iT1, WF1, b1, F1, nullptr, nullptr, nullptr, N);

    // down: K=8, 64->32, relu
    launch_tf32<8, 64, 32, 256, true, false, false, 0>(
        F1, iTd, WFd, bd, D0, nullptr, nullptr, nullptr, N2);

    float* bufs[2] = { D0, D1 };
    for (int i = 0; i < 3; i++) {
        float* in = bufs[i & 1];
        float* ob = bufs[(i + 1) & 1];

        // K1: a8 = relu(conv27(in, rw00)); t8 = relu(in @ rw10)  (fused, k=13 center)
        launch_tf32<27, 32, 8, 256, true, false, true, 13>(
            in, iT2, WF0 + (size_t)i * 27 * 256, rb00 + i * 8, A8,
            WFp + (size_t)i * 256, rb10 + i * 8, T8, N2);

        // K2: ob[:, :16] = conv27(a8, rw01) + rb01 + in[:, :16];
        //     T8B = relu(conv27(t8, rw11) + rb11)
        spconv_dual8<27><<<(N2 + 255) / 256, 256>>>(
            A8, T8, iT2,
            rw01 + (size_t)i * 27 * 8 * 16, rb01 + i * 16,
            rw11 + (size_t)i * 27 * 8 * 8,  rb11 + i * 8,
            in, ob, T8B, N2);

        // K3: ob[:, 16:] = T8B @ rw12 + rb12 + in[:, 16:]
        pw_kernel<8, 16, false, true, 32, 16><<<(N2 + 255) / 256, 256>>>(
            T8B, rw12 + i * 8 * 16, rb12 + i * 16, in, ob, N2);
    }

    // enc4: K=27, 32->8, no relu, straight to output
    launch_tf32<27, 32, 8, 256, false, false, false, 0>(
        bufs[1], iT2, WF4, b4, (float*)d_out, nullptr, nullptr, nullptr, N2);
}

// round 7
// speedup vs baseline: 1.1467x; 1.1467x over previous
#include <cuda_runtime.h>
#include <cuda_bf16.h>

typedef unsigned long long u64;
typedef unsigned int u32;

#define MAXN 250048

// Scratch (allocation-free rule: __device__ globals)
__device__ float g_X  [(size_t)MAXN * 64];
__device__ float g_F1 [(size_t)MAXN * 64];
__device__ float g_D0 [(size_t)MAXN * 32];
__device__ float g_D1 [(size_t)MAXN * 32];
__device__ float g_A8 [(size_t)MAXN * 8];
__device__ float g_T8 [(size_t)MAXN * 8];
__device__ int   g_iT1[(size_t)MAXN * 27];
__device__ int   g_iT2[(size_t)MAXN * 27];
__device__ int   g_iTd[(size_t)MAXN * 8];
// fragment-packed tf32 weights
__device__ float g_WF1[27 * 4096];   // conv1
__device__ float g_WFd[8 * 2048];    // down
__device__ float g_WF0[81 * 256];    // rw00 (3 blocks as K=81)
__device__ float g_WF4[27 * 256];    // enc4
__device__ float g_WFp[3 * 256];     // rw10 pointwise (3 blocks, K=1)

__device__ __forceinline__ u64 pack2(float x) {
    u64 r;
    asm("mov.b64 %0, {%1, %1};" : "=l"(r) : "r"(__float_as_uint(x)));
    return r;
}
__device__ __forceinline__ void fma2(u64& acc, u64 a, u64 b) {
    asm("fma.rn.f32x2 %0, %1, %2, %0;" : "+l"(acc) : "l"(a), "l"(b));
}
__device__ __forceinline__ float2 unpack2(u64 v) {
    float2 r;
    r.x = __uint_as_float((u32)(v & 0xffffffffull));
    r.y = __uint_as_float((u32)(v >> 32));
    return r;
}
__device__ __forceinline__ u32 smem_u32(const void* p) {
    return (u32)__cvta_generic_to_shared(p);
}
__device__ __forceinline__ void cpasync16(u32 dst, const void* src, u32 ssz) {
    asm volatile("cp.async.ca.shared.global [%0], [%1], 16, %2;\n"
                 :: "r"(dst), "l"(src), "r"(ssz));
}
__device__ __forceinline__ void cp_commit() {
    asm volatile("cp.async.commit_group;\n");
}
template<int N>
__device__ __forceinline__ void cp_wait() {
    asm volatile("cp.async.wait_group %0;\n" :: "n"(N));
}
__device__ __forceinline__ float rna_tf32(float x) {
    u32 y;
    asm("cvt.rna.tf32.f32 %0, %1;" : "=r"(y) : "f"(x));
    return __uint_as_float(y);
}
__device__ __forceinline__ void mma8(float4& d, const float* a, float2 b) {
    asm("mma.sync.aligned.m16n8k8.row.col.f32.tf32.tf32.f32 "
        "{%0,%1,%2,%3}, {%4,%5,%6,%7}, {%8,%9}, {%0,%1,%2,%3};"
        : "+f"(d.x), "+f"(d.y), "+f"(d.z), "+f"(d.w)
        : "r"(__float_as_uint(a[0])), "r"(__float_as_uint(a[1])),
          "r"(__float_as_uint(a[2])), "r"(__float_as_uint(a[3])),
          "r"(__float_as_uint(b.x)),  "r"(__float_as_uint(b.y)));
}

// ---------------------------------------------------------------------------
__global__ void transpose_idx(const int* __restrict__ in, int* __restrict__ outT,
                              int Npt, int K)
{
    int p = blockIdx.x * blockDim.x + threadIdx.x;
    if (p < Npt)
        for (int k = 0; k < K; k++)
            outT[(size_t)k * Npt + p] = in[(size_t)p * K + k];
}

// W[k][ci][co] fp32 -> tf32 B-fragment order
__global__ void prep_wfrag(const float* __restrict__ W, float* __restrict__ Wf,
                           int K, int CIN, int COUT)
{
    int Q = CIN / 8, NT = COUT / 8;
    int total = K * Q * NT * 64;
    int e = blockIdx.x * 256 + threadIdx.x;
    if (e >= total) return;
    int j = e & 1;
    int lane = (e >> 1) & 31;
    int r = e >> 6;
    int nt = r % NT; r /= NT;
    int q = r % Q;  int k = r / Q;
    int ci = q * 8 + (lane & 3) + 4 * j;
    int co = nt * 8 + (lane >> 2);
    Wf[e] = rna_tf32(W[((size_t)k * CIN + ci) * COUT + co]);
}

// ---------------------------------------------------------------------------
// tf32 mma.sync gather-GEMM sparse conv.  128 points/CTA (=128 threads),
// 4 warps; warp w -> rows [32w,32w+32) as 2 m16 tiles.
// cp.async double-buffered over K offsets; accumulate across offsets in regs.
// FUSEPW: at k==CK (center offset), also accumulate pointwise Wp (COUT=8)
// producing tp = relu(in[p] @ Wp + Bp) -> Tout.
// ---------------------------------------------------------------------------
template<int K, int CIN, int COUT, bool RELU, bool CVTOUT, bool FUSEPW, int CK>
__global__ void __launch_bounds__(128)
tf32_conv(const float* __restrict__ X, const int* __restrict__ idxT,
          const float* __restrict__ Wf, const float* __restrict__ Bb,
          float* __restrict__ out,
          const float* __restrict__ Wp, const float* __restrict__ Bp,
          float* __restrict__ Tout, int Nout)
{
    constexpr int NTHR = 128;
    constexpr int Q    = CIN / 8;
    constexpr int NT   = COUT / 8;
    constexpr int ASTG = NTHR * CIN;
    constexpr int WSTG = Q * NT * 64;
    constexpr int C4U  = CIN / 4;

    extern __shared__ float sm[];
    float* A0 = sm;
    float* A1 = sm + ASTG;
    float* W0 = sm + 2 * ASTG;
    float* W1 = W0 + WSTG;

    const int tid = threadIdx.x, wid = tid >> 5, lane = tid & 31;
    const int r7 = lane >> 2;
    const int cl = lane & 3;
    const int p0 = blockIdx.x * NTHR;
    const int gp = p0 + tid;
    const bool pv = gp < Nout;

    const u32 ab0 = smem_u32(A0), ab1 = smem_u32(A1);
    const u32 wb0 = smem_u32(W0), wb1 = smem_u32(W1);

    // pointwise B fragments (small, L2-resident)
    float2 b10[FUSEPW ? Q : 1];
    if (FUSEPW) {
#pragma unroll
        for (int q = 0; q < Q; q++)
            b10[q] = *(const float2*)(Wp + (q * 32 + lane) * 2);
    }

    auto prefetch = [&](int k, int b) {
        int src = pv ? idxT[(size_t)k * Nout + gp] : -1;
        const float* srow = X + (size_t)(src >= 0 ? src : 0) * CIN;
        u32 ssz = (src >= 0) ? 16u : 0u;
        u32 base = (b ? ab1 : ab0) + (u32)tid * (CIN * 4);
#pragma unroll
        for (int c4 = 0; c4 < C4U; c4++)
            cpasync16(base + ((u32)(c4 ^ (tid & 7)) << 4), srow + 4 * c4, ssz);
        const float4* wg = (const float4*)(Wf + (size_t)k * WSTG);
        u32 wdst = b ? wb1 : wb0;
        for (int e = tid; e < WSTG / 4; e += NTHR)
            cpasync16(wdst + 16u * e, wg + e, 16);
    };

    prefetch(0, 0);
    cp_commit();

    float4 acc[2][NT];
#pragma unroll
    for (int m = 0; m < 2; m++)
#pragma unroll
        for (int nt = 0; nt < NT; nt++)
            acc[m][nt] = make_float4(0.f, 0.f, 0.f, 0.f);
    float4 acc2[2];
    acc2[0] = acc2[1] = make_float4(0.f, 0.f, 0.f, 0.f);

#pragma unroll 1
    for (int k = 0; k < K; k++) {
        __syncthreads();
        if (k + 1 < K) { prefetch(k + 1, (k + 1) & 1); cp_commit(); cp_wait<1>(); }
        else           { cp_wait<0>(); }
        __syncthreads();

        const float* A  = (k & 1) ? A1 : A0;
        const float* Wk = (k & 1) ? W1 : W0;

#pragma unroll
        for (int q = 0; q < Q; q++) {
            const int c4a = ((2 * q) ^ r7) << 2;
            const int c4b = ((2 * q + 1) ^ r7) << 2;
            float a[2][4];
#pragma unroll
            for (int m = 0; m < 2; m++) {
                const int rl = wid * 32 + m * 16 + r7;
                a[m][0] = A[rl * CIN + c4a + cl];
                a[m][1] = A[(rl + 8) * CIN + c4a + cl];
                a[m][2] = A[rl * CIN + c4b + cl];
                a[m][3] = A[(rl + 8) * CIN + c4b + cl];
            }
#pragma unroll
            for (int nt = 0; nt < NT; nt++) {
                float2 b = *(const float2*)(Wk + ((q * NT + nt) * 32 + lane) * 2);
                mma8(acc[0][nt], a[0], b);
                mma8(acc[1][nt], a[1], b);
            }
            if (FUSEPW && k == CK) {
                mma8(acc2[0], a[0], b10[q]);
                mma8(acc2[1], a[1], b10[q]);
            }
        }
    }

    // epilogue
#pragma unroll
    for (int m = 0; m < 2; m++) {
        const int rlo = p0 + wid * 32 + m * 16 + r7;
        const int rhi = rlo + 8;
#pragma unroll
        for (int nt = 0; nt < NT; nt++) {
            const int c0 = nt * 8 + 2 * cl;
            const float b0 = Bb[c0], b1 = Bb[c0 + 1];
            float2 v0 = make_float2(acc[m][nt].x + b0, acc[m][nt].y + b1);
            float2 v1 = make_float2(acc[m][nt].z + b0, acc[m][nt].w + b1);
            if (RELU) {
                v0.x = fmaxf(v0.x, 0.f); v0.y = fmaxf(v0.y, 0.f);
                v1.x = fmaxf(v1.x, 0.f); v1.y = fmaxf(v1.y, 0.f);
            }
            if (CVTOUT) {
                v0.x = rna_tf32(v0.x); v0.y = rna_tf32(v0.y);
                v1.x = rna_tf32(v1.x); v1.y = rna_tf32(v1.y);
            }
            if (rlo < Nout) *(float2*)(out + (size_t)rlo * COUT + c0) = v0;
            if (rhi < Nout) *(float2*)(out + (size_t)rhi * COUT + c0) = v1;
        }
        if (FUSEPW) {
            const int c0 = 2 * cl;
            const float b0 = Bp[c0], b1 = Bp[c0 + 1];
            float2 v0 = make_float2(fmaxf(acc2[m].x + b0, 0.f),
                                    fmaxf(acc2[m].y + b1, 0.f));
            float2 v1 = make_float2(fmaxf(acc2[m].z + b0, 0.f),
                                    fmaxf(acc2[m].w + b1, 0.f));
            if (rlo < Nout) *(float2*)(Tout + (size_t)rlo * 8 + c0) = v0;
            if (rhi < Nout) *(float2*)(Tout + (size_t)rhi * 8 + c0) = v1;
        }
    }
}

// ---------------------------------------------------------------------------
// Fused inception tail over one idx2 walk:
//   acc0 = conv27(A8, W01) + b01           (COUT=16)
//   t    = relu(conv27(T8, W11) + b11)     (COUT=8, kept in registers)
//   out1 = t @ W12 + b12                   (pointwise, 8->16)
//   ob[p, 0:16]  = acc0 + Rin[p, 0:16]
//   ob[p, 16:32] = out1 + Rin[p, 16:32]
// ---------------------------------------------------------------------------
template<int K>
__global__ void __launch_bounds__(256)
spconv_tail(const float* __restrict__ A8, const float* __restrict__ T8,
            const int* __restrict__ idxT,
            const float* __restrict__ W01, const float* __restrict__ b01,
            const float* __restrict__ W11, const float* __restrict__ b11,
            const float* __restrict__ W12, const float* __restrict__ b12,
            const float* __restrict__ Rin, float* __restrict__ ob, int Nout)
{
    __shared__ float Wsh0[K * 8 * 16];
    __shared__ float Wsh1[K * 8 * 8];
    __shared__ float Wsh2[8 * 16];
    for (int e = threadIdx.x; e < K * 8 * 16; e += 256) Wsh0[e] = W01[e];
    for (int e = threadIdx.x; e < K * 8 * 8; e += 256)  Wsh1[e] = W11[e];
    if (threadIdx.x < 128) Wsh2[threadIdx.x] = W12[threadIdx.x];
    __syncthreads();

    const int p = blockIdx.x * 256 + threadIdx.x;
    if (p >= Nout) return;

    u64 acc0[8], acc1[4];
#pragma unroll
    for (int c = 0; c < 8; c++) acc0[c] = 0ull;
#pragma unroll
    for (int c = 0; c < 4; c++) acc1[c] = 0ull;

    const float4 z4 = make_float4(0.f, 0.f, 0.f, 0.f);
    int s_nxt = (K > 1) ? idxT[(size_t)Nout + p] : -1;
    int s0 = idxT[p];
    float4 a0 = z4, a1 = z4, t0 = z4, t1 = z4;
    if (s0 >= 0) {
        const float4* ra = (const float4*)(A8 + (size_t)s0 * 8);
        a0 = ra[0]; a1 = ra[1];
        const float4* rt = (const float4*)(T8 + (size_t)s0 * 8);
        t0 = rt[0]; t1 = rt[1];
    }

#pragma unroll 1
    for (int k = 0; k < K; k++) {
        float4 na0 = z4, na1 = z4, nt0 = z4, nt1 = z4;
        if (k + 1 < K) {
            if (s_nxt >= 0) {
                const float4* ra = (const float4*)(A8 + (size_t)s_nxt * 8);
                na0 = ra[0]; na1 = ra[1];
                const float4* rt = (const float4*)(T8 + (size_t)s_nxt * 8);
                nt0 = rt[0]; nt1 = rt[1];
            }
            s_nxt = (k + 2 < K) ? idxT[(size_t)(k + 2) * Nout + p] : -1;
        }
        {
            const float* wk = Wsh0 + k * 8 * 16;
            const float ga[8] = { a0.x, a0.y, a0.z, a0.w, a1.x, a1.y, a1.z, a1.w };
#pragma unroll
            for (int ci = 0; ci < 8; ci++) {
                u64 g2 = pack2(ga[ci]);
                const u64* wr = (const u64*)(wk + ci * 16);
#pragma unroll
                for (int cc = 0; cc < 8; cc++) fma2(acc0[cc], g2, wr[cc]);
            }
        }
        {
            const float* wk = Wsh1 + k * 8 * 8;
            const float gt[8] = { t0.x, t0.y, t0.z, t0.w, t1.x, t1.y, t1.z, t1.w };
#pragma unroll
            for (int ci = 0; ci < 8; ci++) {
                u64 g2 = pack2(gt[ci]);
                const u64* wr = (const u64*)(wk + ci * 8);
#pragma unroll
                for (int cc = 0; cc < 4; cc++) fma2(acc1[cc], g2, wr[cc]);
            }
        }
        a0 = na0; a1 = na1; t0 = nt0; t1 = nt1;
    }

    // t = relu(acc1 + b11)
    float t[8];
#pragma unroll
    for (int q = 0; q < 4; q++) {
        float2 v = unpack2(acc1[q]);
        t[2 * q]     = fmaxf(v.x + b11[2 * q], 0.f);
        t[2 * q + 1] = fmaxf(v.y + b11[2 * q + 1], 0.f);
    }

    // out1 = t @ W12 + b12 (pointwise 8->16, f32x2 across COUT pairs)
    u64 acc2[8];
#pragma unroll
    for (int c = 0; c < 8; c++) acc2[c] = 0ull;
#pragma unroll
    for (int ci = 0; ci < 8; ci++) {
        u64 g2 = pack2(t[ci]);
        const u64* wr = (const u64*)(Wsh2 + ci * 16);
#pragma unroll
        for (int cc = 0; cc < 8; cc++) fma2(acc2[cc], g2, wr[cc]);
    }

    // ob[p, 0:16] = acc0 + b01 + Rin[:, :16];  ob[p, 16:32] = acc2 + b12 + Rin[:, 16:]
    float* op = ob + (size_t)p * 32;
#pragma unroll
    for (int q = 0; q < 4; q++) {
        float2 v0 = unpack2(acc0[2 * q]);
        float2 v1 = unpack2(acc0[2 * q + 1]);
        float4 o = make_float4(v0.x + b01[4 * q], v0.y + b01[4 * q + 1],
                               v1.x + b01[4 * q + 2], v1.y + b01[4 * q + 3]);
        float4 r = *(const float4*)(Rin + (size_t)p * 32 + 4 * q);
        o.x += r.x; o.y += r.y; o.z += r.z; o.w += r.w;
        *(float4*)(op + 4 * q) = o;
    }
#pragma unroll
    for (int q = 0; q < 4; q++) {
        float2 v0 = unpack2(acc2[2 * q]);
        float2 v1 = unpack2(acc2[2 * q + 1]);
        float4 o = make_float4(v0.x + b12[4 * q], v0.y + b12[4 * q + 1],
                               v1.x + b12[4 * q + 2], v1.y + b12[4 * q + 3]);
        float4 r = *(const float4*)(Rin + (size_t)p * 32 + 16 + 4 * q);
        o.x += r.x; o.y += r.y; o.z += r.z; o.w += r.w;
        *(float4*)(op + 16 + 4 * q) = o;
    }
}

template<bool CVT>
__global__ void add_kernel(const float* __restrict__ a, const float* __restrict__ b,
                           float* __restrict__ o, long long n4)
{
    long long i = blockIdx.x * (long long)blockDim.x + threadIdx.x;
    if (i < n4) {
        float4 x = ((const float4*)a)[i];
        float4 y = ((const float4*)b)[i];
        x.x += y.x; x.y += y.y; x.z += y.z; x.w += y.w;
        if (CVT) {
            x.x = rna_tf32(x.x); x.y = rna_tf32(x.y);
            x.z = rna_tf32(x.z); x.w = rna_tf32(x.w);
        }
        ((float4*)o)[i] = x;
    }
}

// ---------------------------------------------------------------------------
template<int K, int CIN, int COUT, bool RELU, bool CVTOUT, bool FUSEPW, int CK>
static void launch_tf32(const float* X, const int* idxT, const float* Wf,
                        const float* B, float* out,
                        const float* Wp, const float* Bp, float* Tout, int Nout)
{
    constexpr int SMEM = (2 * 128 * CIN + 2 * (CIN / 8) * (COUT / 8) * 64) * 4;
    auto kfn = tf32_conv<K, CIN, COUT, RELU, CVTOUT, FUSEPW, CK>;
    cudaFuncSetAttribute(kfn, cudaFuncAttributeMaxDynamicSharedMemorySize, SMEM);
    int grid = (Nout + 127) / 128;
    kfn<<<grid, 128, SMEM>>>(X, idxT, Wf, B, out, Wp, Bp, Tout, Nout);
}

extern "C" void kernel_launch(void* const* d_in, const int* in_sizes, int n_in,
                              void* d_out, int out_size)
{
    const float* x_feat = (const float*)d_in[0];
    const float* f1_ref = (const float*)d_in[1];
    const float* w1   = (const float*)d_in[2];
    const float* b1   = (const float*)d_in[3];
    const float* wd   = (const float*)d_in[4];
    const float* bd   = (const float*)d_in[5];
    const float* rw00 = (const float*)d_in[6];
    const float* rb00 = (const float*)d_in[7];
    const float* rw01 = (const float*)d_in[8];
    const float* rb01 = (const float*)d_in[9];
    const float* rw10 = (const float*)d_in[10];
    const float* rb10 = (const float*)d_in[11];
    const float* rw11 = (const float*)d_in[12];
    const float* rb11 = (const float*)d_in[13];
    const float* rw12 = (const float*)d_in[14];
    const float* rb12 = (const float*)d_in[15];
    const float* w4   = (const float*)d_in[16];
    const float* b4   = (const float*)d_in[17];
    const int* idx1 = (const int*)d_in[18];
    const int* idxd = (const int*)d_in[19];
    const int* idx2 = (const int*)d_in[20];

    int N  = in_sizes[0] / 64;
    int N2 = in_sizes[19] / 8;

    float *X, *F1, *D0, *D1, *A8, *T8;
    float *WF1, *WFd, *WF0, *WF4, *WFp;
    int *iT1, *iT2, *iTd;
    cudaGetSymbolAddress((void**)&X,   g_X);
    cudaGetSymbolAddress((void**)&F1,  g_F1);
    cudaGetSymbolAddress((void**)&D0,  g_D0);
    cudaGetSymbolAddress((void**)&D1,  g_D1);
    cudaGetSymbolAddress((void**)&A8,  g_A8);
    cudaGetSymbolAddress((void**)&T8,  g_T8);
    cudaGetSymbolAddress((void**)&iT1, g_iT1);
    cudaGetSymbolAddress((void**)&iT2, g_iT2);
    cudaGetSymbolAddress((void**)&iTd, g_iTd);
    cudaGetSymbolAddress((void**)&WF1, g_WF1);
    cudaGetSymbolAddress((void**)&WFd, g_WFd);
    cudaGetSymbolAddress((void**)&WF0, g_WF0);
    cudaGetSymbolAddress((void**)&WF4, g_WF4);
    cudaGetSymbolAddress((void**)&WFp, g_WFp);

    // prep
    transpose_idx<<<(N  + 255) / 256, 256>>>(idx1, iT1, N,  27);
    transpose_idx<<<(N2 + 255) / 256, 256>>>(idxd, iTd, N2, 8);
    transpose_idx<<<(N2 + 255) / 256, 256>>>(idx2, iT2, N2, 27);
    prep_wfrag<<<(27 * 4096 + 255) / 256, 256>>>(w1,   WF1, 27, 64, 64);
    prep_wfrag<<<(8 * 2048 + 255) / 256, 256>>>(wd,    WFd, 8,  64, 32);
    prep_wfrag<<<(81 * 256 + 255) / 256, 256>>>(rw00,  WF0, 81, 32, 8);
    prep_wfrag<<<(27 * 256 + 255) / 256, 256>>>(w4,    WF4, 27, 32, 8);
    prep_wfrag<<<(3 * 256 + 255) / 256, 256>>>(rw10,   WFp, 3,  32, 8);

    // x = tf32(x_feat + f1_ref)
    long long n4 = (long long)N * 16;
    add_kernel<true><<<(int)((n4 + 255) / 256), 256>>>(x_feat, f1_ref, X, n4);

    // conv1: K=27, 64->64, relu (rounds output to tf32 for `down`)
    launch_tf32<27, 64, 64, true, true, false, 0>(
        X, iT1, WF1, b1, F1, nullptr, nullptr, nullptr, N);

    // down: K=8, 64->32, relu
    launch_tf32<8, 64, 32, true, false, false, 0>(
        F1, iTd, WFd, bd, D0, nullptr, nullptr, nullptr, N2);

    float* bufs[2] = { D0, D1 };
    for (int i = 0; i < 3; i++) {
        float* in = bufs[i & 1];
        float* ob = bufs[(i + 1) & 1];

        // K1: a8 = relu(conv27(in, rw00)); t8 = relu(in @ rw10)  (fused, k=13 center)
        launch_tf32<27, 32, 8, true, false, true, 13>(
            in, iT2, WF0 + (size_t)i * 27 * 256, rb00 + i * 8, A8,
            WFp + (size_t)i * 256, rb10 + i * 8, T8, N2);

        // K2: full inception tail (rw01 conv + rw11 conv + rw12 pw + resid)
        spconv_tail<27><<<(N2 + 255) / 256, 256>>>(
            A8, T8, iT2,
            rw01 + (size_t)i * 27 * 8 * 16, rb01 + i * 16,
            rw11 + (size_t)i * 27 * 8 * 8,  rb11 + i * 8,
            rw12 + (size_t)i * 8 * 16,      rb12 + i * 16,
            in, ob, N2);
    }

    // enc4: K=27, 32->8, no relu, straight to output
    launch_tf32<27, 32, 8, false, false, false, 0>(
        bufs[1], iT2, WF4, b4, (float*)d_out, nullptr, nullptr, nullptr, N2);
}